// round 8
// baseline (speedup 1.0000x reference)
#include <cuda_runtime.h>

// Problem constants
#define BATCH 32
#define SEQ   512
#define DIM   64
#define VOCAB 32000
#define DECAY 0.9f

#define T_CHUNK 32
#define NCHUNK  16                      // SEQ / T_CHUNK
#define DC      0.03433683820292512f    // 0.9^32 (chunk decay)
#define MTERMS  4                       // carry terms kept; err ~0.9^128 = 1.4e-6

// Scratch: per-chunk local sums L_k [B][NCHUNK][D][D] = 8 MB (L2-resident)
__device__ float g_L[BATCH * NCHUNK * DIM * DIM];

// Gather one chunk's 32 token embeddings into smem: sc[s][d] (2 float4/thread)
__device__ __forceinline__ void gather_chunk(const int* __restrict__ x,
                                             const float* __restrict__ emb,
                                             float* sc, int b, int k, int tid) {
    #pragma unroll
    for (int h = 0; h < 2; h++) {
        const int q  = tid + h * 256;  // float4 index 0..511
        const int s  = q >> 4;         // token within chunk
        const int d4 = q & 15;
        int tok = x[b * SEQ + k * T_CHUNK + s];
        tok = min(max(tok, 0), VOCAB - 1);
        reinterpret_cast<float4*>(sc)[q] =
            reinterpret_cast<const float4*>(emb + (size_t)tok * DIM)[d4];
    }
}

// ---------------------------------------------------------------------------
// Kernel B1: gather + per-chunk local decayed sums.
//   L_k[i][j] = sum_t DECAY^{T-1-t} * c_t[i] * c_t[j]
// Grid 512 blocks, 256 thr; thread owns a 4x4 tile.
// ---------------------------------------------------------------------------
__global__ __launch_bounds__(256, 4)
void qmn_chunk_sum(const int* __restrict__ x, const float* __restrict__ emb) {
    __shared__ __align__(16) float sc[T_CHUNK * DIM];   // 8 KB

    const int b   = blockIdx.x >> 4;
    const int k   = blockIdx.x & 15;
    const int tid = threadIdx.x;

    gather_chunk(x, emb, sc, b, k, tid);
    __syncthreads();

    const int i0 = (tid >> 4) * 4;
    const int j0 = (tid & 15) * 4;

    float4 L[4];
    #pragma unroll
    for (int r = 0; r < 4; r++) L[r] = make_float4(0.f, 0.f, 0.f, 0.f);

    #pragma unroll 8
    for (int t = 0; t < T_CHUNK; t++) {
        const float4 ci = *reinterpret_cast<const float4*>(sc + t * DIM + i0);
        const float4 cj = *reinterpret_cast<const float4*>(sc + t * DIM + j0);
        const float c[4] = {ci.x, ci.y, ci.z, ci.w};
        #pragma unroll
        for (int r = 0; r < 4; r++) {
            L[r].x = fmaf(L[r].x, DECAY, c[r] * cj.x);
            L[r].y = fmaf(L[r].y, DECAY, c[r] * cj.y);
            L[r].z = fmaf(L[r].z, DECAY, c[r] * cj.z);
            L[r].w = fmaf(L[r].w, DECAY, c[r] * cj.w);
        }
    }

    float* Lp = g_L + (size_t)blockIdx.x * DIM * DIM;
    #pragma unroll
    for (int r = 0; r < 4; r++)
        __stcg(reinterpret_cast<float4*>(Lp + (i0 + r) * DIM + j0), L[r]);
}

// ---------------------------------------------------------------------------
// Kernel C: state emission, single wave (512 blocks).
// Carry-in from the last MTERMS L's (geometric truncation), then 32
// barrier-free emit steps with streaming stores.
// ---------------------------------------------------------------------------
__global__ __launch_bounds__(256, 4)
void qmn_states(const int* __restrict__ x, const float* __restrict__ emb,
                float* __restrict__ out) {
    __shared__ __align__(16) float sc[T_CHUNK * DIM];   // 8 KB

    const int b   = blockIdx.x >> 4;
    const int k   = blockIdx.x & 15;
    const int tid = threadIdx.x;

    const int i0 = (tid >> 4) * 4;
    const int j0 = (tid & 15) * 4;

    // ---- Truncated carry (issued before the smem barrier so the L2 loads
    //      overlap the gather): acc = sum_m DC^{k-1-m} L_m (+ DC^k I) ----
    float4 acc[4];
    #pragma unroll
    for (int r = 0; r < 4; r++) acc[r] = make_float4(0.f, 0.f, 0.f, 0.f);

    const float* Lb = g_L + (size_t)b * NCHUNK * DIM * DIM;
    const int mlo = (k - MTERMS > 0) ? (k - MTERMS) : 0;
    float w = 1.0f;
    for (int m = k - 1; m >= mlo; m--) {
        const float* Lp = Lb + (size_t)m * DIM * DIM;
        #pragma unroll
        for (int r = 0; r < 4; r++) {
            const float4 l = *reinterpret_cast<const float4*>(Lp + (i0 + r) * DIM + j0);
            acc[r].x = fmaf(w, l.x, acc[r].x);
            acc[r].y = fmaf(w, l.y, acc[r].y);
            acc[r].z = fmaf(w, l.z, acc[r].z);
            acc[r].w = fmaf(w, l.w, acc[r].w);
        }
        w *= DC;
    }
    if (k <= MTERMS) {                 // loop ran k times -> w == DC^k
        #pragma unroll
        for (int r = 0; r < 4; r++) {
            const int i = i0 + r;
            if (i == j0 + 0) acc[r].x += w;
            if (i == j0 + 1) acc[r].y += w;
            if (i == j0 + 2) acc[r].z += w;
            if (i == j0 + 3) acc[r].w += w;
        }
    }

    gather_chunk(x, emb, sc, b, k, tid);
    __syncthreads();

    // ---- Emit 32 states, barrier-free, streaming stores ----
    float* op = out + ((size_t)b * SEQ + (size_t)k * T_CHUNK) * DIM * DIM;

    #pragma unroll 4
    for (int t = 0; t < T_CHUNK; t++) {
        const float4 ci = *reinterpret_cast<const float4*>(sc + t * DIM + i0);
        const float4 cj = *reinterpret_cast<const float4*>(sc + t * DIM + j0);
        const float c[4] = {ci.x, ci.y, ci.z, ci.w};
        #pragma unroll
        for (int r = 0; r < 4; r++) {
            acc[r].x = fmaf(acc[r].x, DECAY, c[r] * cj.x);
            acc[r].y = fmaf(acc[r].y, DECAY, c[r] * cj.y);
            acc[r].z = fmaf(acc[r].z, DECAY, c[r] * cj.z);
            acc[r].w = fmaf(acc[r].w, DECAY, c[r] * cj.w);
        }
        float* ot = op + (size_t)t * DIM * DIM;
        #pragma unroll
        for (int r = 0; r < 4; r++)
            __stcs(reinterpret_cast<float4*>(ot + (i0 + r) * DIM + j0), acc[r]);
    }
}

// ---------------------------------------------------------------------------
// Launch
// ---------------------------------------------------------------------------
extern "C" void kernel_launch(void* const* d_in, const int* in_sizes, int n_in,
                              void* d_out, int out_size) {
    const int*   x   = (const int*)d_in[0];     // [B, S] int32
    const float* emb = (const float*)d_in[1];   // [VOCAB, D] fp32
    float*       out = (float*)d_out;           // [B, S, D, D] fp32

    (void)in_sizes; (void)n_in; (void)out_size;

    qmn_chunk_sum<<<BATCH * NCHUNK, 256>>>(x, emb);
    qmn_states<<<BATCH * NCHUNK, 256>>>(x, emb, out);
}